// round 5
// baseline (speedup 1.0000x reference)
#include <cuda_runtime.h>
#include <cuda_fp16.h>
#include <cstdint>

// Problem constants
#define BB 4
#define SS 2048
#define DD 1024
#define MM (BB * SS)   // 8192

#define NEG_INF (__int_as_float(0xff800000))

// GEMM tiling: CTA 128x256, 16 warps (512 thr) of 32x64, BK=64 fp16, 3 stages
#define CTA_M 128
#define CTA_N 256
#define BK 64
#define TPB 512
#define NSTAGE 3
#define A_BYTES (CTA_M * 128)             // 128 rows x 128B (64 fp16)
#define B_BYTES (CTA_N * 128)             // 256 rows x 128B
#define STAGE_BYTES (A_BYTES + B_BYTES)   // 49152
#define SMEM_DYN (NSTAGE * STAGE_BYTES + 1024)

// -------- device scratch (allocation-free rule: __device__ globals) --------
__device__ __half g_xh [(size_t)MM * DD];
__device__ __half g_Wth[(size_t)3 * DD * DD];     // [z][n][k] = W[z][k][n]
__device__ __half g_Qh [(size_t)MM * DD];
__device__ __half g_Kh [(size_t)MM * DD];
__device__ __half g_Vh [(size_t)MM * DD];
__device__ __half g_Vth[(size_t)BB * DD * SS];    // [b][d][s]
__device__ float  g_P  [(size_t)BB * SS * SS];    // fp32 scores
__device__ __half g_Ph [(size_t)BB * SS * SS];    // fp16 probabilities

__device__ __forceinline__ uint32_t smem_u32(const void* p) {
    uint32_t a;
    asm("{ .reg .u64 t; cvta.to.shared.u64 t, %1; cvt.u32.u64 %0, t; }" : "=r"(a) : "l"(p));
    return a;
}
#define SWZ128(x) ((x) ^ (((x) >> 3) & 0x70u))

// ---------------------------------------------------------------------------
// fp16 tensor-core mainloop. CTA computes 128x256.
// A row-major [128][lda] fp16; B row-major [256][ldb] fp16 (rows = N dim).
// Warp (wid&3)->M row block of 32, (wid>>2)->N col block of 64.
// acc[i][j][4]: 2 m16 x 8 n8 tiles.
// ---------------------------------------------------------------------------
__device__ __forceinline__ void gemm_f16(
    const __half* __restrict__ A, const __half* __restrict__ B,
    int lda, int ldb, int kTotal, float acc[2][8][4])
{
    extern __shared__ char smem_raw[];
    const uint32_t base = (smem_u32(smem_raw) + 1023) & ~1023u;
    const int tid = threadIdx.x, L = tid & 31, wid = tid >> 5;
    const int wm = (wid & 3) * 32, wn = (wid >> 2) * 64;

    // ldmatrix source coordinates (row, 16B col-base), stage-relative, unswizzled
    const uint32_t aRow = (uint32_t)(wm + (L & 15));
    const uint32_t aCol = (uint32_t)((L >> 4) * 16);
    const uint32_t bRow = (uint32_t)(wn + ((L >> 4) & 1) * 8 + (L & 7));
    const uint32_t bCol = (uint32_t)(((L >> 3) & 1) * 16);

    const int nslab = kTotal / BK;

    auto issue = [&](int s) {
        const uint32_t sb = base + (uint32_t)(s % NSTAGE) * STAGE_BYTES;
        const int k0 = s * BK;
        #pragma unroll
        for (int i = 0; i < 2; ++i) {               // A: 1024 16B chunks
            const int g = i * TPB + tid;
            const int row = g >> 3, ch = g & 7;
            const uint32_t dst = sb + SWZ128((uint32_t)row * 128u + (uint32_t)ch * 16u);
            const __half* src = A + (size_t)row * lda + k0 + ch * 8;
            asm volatile("cp.async.cg.shared.global [%0], [%1], 16;" :: "r"(dst), "l"(src));
        }
        #pragma unroll
        for (int i = 0; i < 4; ++i) {               // B: 2048 16B chunks
            const int g = i * TPB + tid;
            const int row = g >> 3, ch = g & 7;
            const uint32_t dst = sb + (uint32_t)A_BYTES
                               + SWZ128((uint32_t)row * 128u + (uint32_t)ch * 16u);
            const __half* src = B + (size_t)row * ldb + k0 + ch * 8;
            asm volatile("cp.async.cg.shared.global [%0], [%1], 16;" :: "r"(dst), "l"(src));
        }
        asm volatile("cp.async.commit_group;" ::: "memory");
    };

    issue(0); issue(1);

    for (int t = 0; t < nslab; ++t) {
        asm volatile("cp.async.wait_group 1;" ::: "memory");
        __syncthreads();
        if (t + 2 < nslab) issue(t + 2);
        else asm volatile("cp.async.commit_group;" ::: "memory");

        const uint32_t sb = base + (uint32_t)(t % NSTAGE) * STAGE_BYTES;
        #pragma unroll
        for (int h = 0; h < 4; ++h) {               // 4 k16 steps per slab
            uint32_t a[2][4], b[4][4];
            #pragma unroll
            for (int i = 0; i < 2; ++i) {
                const uint32_t o = SWZ128((aRow + i * 16) * 128u + aCol + (uint32_t)h * 32u);
                asm volatile("ldmatrix.sync.aligned.m8n8.x4.shared.b16 {%0,%1,%2,%3}, [%4];"
                    : "=r"(a[i][0]), "=r"(a[i][1]), "=r"(a[i][2]), "=r"(a[i][3])
                    : "r"(sb + o));
            }
            #pragma unroll
            for (int jj = 0; jj < 4; ++jj) {
                const uint32_t o = SWZ128((bRow + jj * 16) * 128u + bCol + (uint32_t)h * 32u);
                asm volatile("ldmatrix.sync.aligned.m8n8.x4.shared.b16 {%0,%1,%2,%3}, [%4];"
                    : "=r"(b[jj][0]), "=r"(b[jj][1]), "=r"(b[jj][2]), "=r"(b[jj][3])
                    : "r"(sb + (uint32_t)A_BYTES + o));
            }
            #pragma unroll
            for (int i = 0; i < 2; ++i)
                #pragma unroll
                for (int j = 0; j < 8; ++j) {
                    asm volatile(
                        "mma.sync.aligned.m16n8k16.row.col.f32.f16.f16.f32 "
                        "{%0,%1,%2,%3},{%4,%5,%6,%7},{%8,%9},{%0,%1,%2,%3};"
                        : "+f"(acc[i][j][0]), "+f"(acc[i][j][1]),
                          "+f"(acc[i][j][2]), "+f"(acc[i][j][3])
                        : "r"(a[i][0]), "r"(a[i][1]), "r"(a[i][2]), "r"(a[i][3]),
                          "r"(b[j >> 1][(j & 1) * 2]), "r"(b[j >> 1][(j & 1) * 2 + 1]));
                }
        }
    }
    asm volatile("cp.async.wait_group 0;" ::: "memory");
}

// ============================ GEMM kernels ============================

// QKV: C[m][n] = sum_k xh[m][k] * Wth[z][n][k].  grid (D/256, M/128, 3)
__global__ __launch_bounds__(TPB, 1) void qkv_f16()
{
    const int m0 = blockIdx.y * CTA_M, n0 = blockIdx.x * CTA_N;
    const __half* Bp = g_Wth + (size_t)blockIdx.z * DD * DD + (size_t)n0 * DD;
    __half* C = (blockIdx.z == 0) ? g_Qh : (blockIdx.z == 1) ? g_Kh : g_Vh;

    float acc[2][8][4] = {};
    gemm_f16(g_xh + (size_t)m0 * DD, Bp, DD, DD, DD, acc);

    const int L = threadIdx.x & 31, wid = threadIdx.x >> 5;
    const int wm = (wid & 3) * 32, wn = (wid >> 2) * 64;
    #pragma unroll
    for (int i = 0; i < 2; ++i) {
        const int row = m0 + wm + i * 16 + (L >> 2);
        #pragma unroll
        for (int j = 0; j < 8; ++j) {
            const int col = n0 + wn + j * 8 + (L & 3) * 2;
            *(__half2*)&C[(size_t)row * DD + col]       = __floats2half2_rn(acc[i][j][0], acc[i][j][1]);
            *(__half2*)&C[(size_t)(row + 8) * DD + col] = __floats2half2_rn(acc[i][j][2], acc[i][j][3]);
        }
    }
}

// scores: P[q][k] = mask(Q·K^T / 32).  grid (S/256 kblk, S/128 qblk, B)
__global__ __launch_bounds__(TPB, 1) void scores_f16()
{
    const int qblk = blockIdx.y, kblk = blockIdx.x, b = blockIdx.z;
    if (2 * kblk >= qblk + 1) return;       // tile fully above diagonal
    const int q0 = qblk * CTA_M, k0 = kblk * CTA_N;

    float acc[2][8][4] = {};
    gemm_f16(g_Qh + ((size_t)b * SS + q0) * DD,
             g_Kh + ((size_t)b * SS + k0) * DD, DD, DD, DD, acc);

    const int L = threadIdx.x & 31, wid = threadIdx.x >> 5;
    const int wm = (wid & 3) * 32, wn = (wid >> 2) * 64;
    float* P = g_P + (size_t)b * SS * SS;
    #pragma unroll
    for (int i = 0; i < 2; ++i) {
        #pragma unroll
        for (int j = 0; j < 8; ++j) {
            const int col = k0 + wn + j * 8 + (L & 3) * 2;
            #pragma unroll
            for (int h = 0; h < 2; ++h) {
                const int row = q0 + wm + i * 16 + (L >> 2) + h * 8;
                float v0 = acc[i][j][2 * h + 0] * 0.03125f;
                float v1 = acc[i][j][2 * h + 1] * 0.03125f;
                if (col > row)     v0 = NEG_INF;
                if (col + 1 > row) v1 = NEG_INF;
                *(float2*)&P[(size_t)row * SS + col] = make_float2(v0, v1);
            }
        }
    }
}

// PV: O[q][n] = sum_k Ph[q][k] * Vth[n][k].  grid (D/256, S/128, B)
__global__ __launch_bounds__(TPB, 1) void pv_f16(float* __restrict__ out)
{
    const int b = blockIdx.z;
    const int q0 = blockIdx.y * CTA_M, n0 = blockIdx.x * CTA_N;
    const int kTotal = (blockIdx.y + 1) * CTA_M;   // causal extent, mult of BK

    float acc[2][8][4] = {};
    gemm_f16(g_Ph + ((size_t)b * SS + q0) * SS,
             g_Vth + ((size_t)b * DD + n0) * SS, SS, SS, kTotal, acc);

    const int L = threadIdx.x & 31, wid = threadIdx.x >> 5;
    const int wm = (wid & 3) * 32, wn = (wid >> 2) * 64;
    float* C = out + (size_t)b * SS * DD;
    #pragma unroll
    for (int i = 0; i < 2; ++i) {
        const int row = q0 + wm + i * 16 + (L >> 2);
        #pragma unroll
        for (int j = 0; j < 8; ++j) {
            const int col = n0 + wn + j * 8 + (L & 3) * 2;
            *(float2*)&C[(size_t)row * DD + col]       = make_float2(acc[i][j][0], acc[i][j][1]);
            *(float2*)&C[(size_t)(row + 8) * DD + col] = make_float2(acc[i][j][2], acc[i][j][3]);
        }
    }
}

// ============================ aux kernels ============================

__global__ void cvt_x_kernel(const float* __restrict__ x)
{
    const size_t i = ((size_t)blockIdx.x * blockDim.x + threadIdx.x) * 4;
    const float4 v = *(const float4*)(x + i);
    *(__half2*)(g_xh + i)     = __floats2half2_rn(v.x, v.y);
    *(__half2*)(g_xh + i + 2) = __floats2half2_rn(v.z, v.w);
}

__global__ void transW_kernel(const float* __restrict__ Wq,
                              const float* __restrict__ Wk,
                              const float* __restrict__ Wv)
{
    __shared__ float tile[32][33];
    const float* W = (blockIdx.z == 0) ? Wq : (blockIdx.z == 1) ? Wk : Wv;
    __half* Wt = g_Wth + (size_t)blockIdx.z * DD * DD;
    const int x0 = blockIdx.x * 32, y0 = blockIdx.y * 32;
    for (int i = threadIdx.y; i < 32; i += 8)
        tile[i][threadIdx.x] = W[(size_t)(y0 + i) * DD + x0 + threadIdx.x];
    __syncthreads();
    for (int i = threadIdx.y; i < 32; i += 8)
        Wt[(size_t)(x0 + i) * DD + y0 + threadIdx.x] = __float2half(tile[threadIdx.x][i]);
}

__global__ void transV_kernel()
{
    __shared__ __half tile[32][33];
    const int b = blockIdx.z;
    const __half* V = g_Vh + (size_t)b * SS * DD;
    __half* Vt = g_Vth + (size_t)b * DD * SS;
    const int d0 = blockIdx.x * 32, s0 = blockIdx.y * 32;
    for (int i = threadIdx.y; i < 32; i += 8)
        tile[i][threadIdx.x] = V[(size_t)(s0 + i) * DD + d0 + threadIdx.x];
    __syncthreads();
    for (int i = threadIdx.y; i < 32; i += 8)
        Vt[(size_t)(d0 + i) * SS + s0 + threadIdx.x] = tile[threadIdx.x][i];
}

// row softmax g_P (fp32) -> g_Ph (fp16); valid region [0, Lp), Lp 128-aligned.
__global__ __launch_bounds__(256) void softmax_kernel()
{
    const int q = blockIdx.x, b = blockIdx.y;
    const float* row = g_P + ((size_t)b * SS + q) * SS;
    __half* orow = g_Ph + ((size_t)b * SS + q) * SS;
    const int Lp = ((q >> 7) + 1) << 7;
    const int tid = threadIdx.x;

    float vals[8];
    float m = NEG_INF;
    #pragma unroll
    for (int i = 0; i < 8; ++i) {
        const int idx = tid + i * 256;
        vals[i] = (idx < Lp) ? row[idx] : NEG_INF;
        m = fmaxf(m, vals[i]);
    }
    __shared__ float red[256];
    red[tid] = m; __syncthreads();
    #pragma unroll
    for (int s = 128; s > 0; s >>= 1) {
        if (tid < s) red[tid] = fmaxf(red[tid], red[tid + s]);
        __syncthreads();
    }
    m = red[0]; __syncthreads();

    float sum = 0.f;
    #pragma unroll
    for (int i = 0; i < 8; ++i) {
        const float t = vals[i] - m;
        vals[i] = (t < -80.f) ? 0.f : __expf(t);
        sum += vals[i];
    }
    red[tid] = sum; __syncthreads();
    #pragma unroll
    for (int s = 128; s > 0; s >>= 1) {
        if (tid < s) red[tid] += red[tid + s];
        __syncthreads();
    }
    const float inv = 1.f / red[0];
    #pragma unroll
    for (int i = 0; i < 8; ++i) {
        const int idx = tid + i * 256;
        if (idx < Lp) orow[idx] = __float2half(vals[i] * inv);
    }
}

// ---------------------------------------------------------------------------
extern "C" void kernel_launch(void* const* d_in, const int* in_sizes, int n_in,
                              void* d_out, int out_size)
{
    const float* x  = (const float*)d_in[0];
    const float* Wq = (const float*)d_in[1];
    const float* Wk = (const float*)d_in[2];
    const float* Wv = (const float*)d_in[3];
    float* out = (float*)d_out;
    (void)in_sizes; (void)n_in; (void)out_size;

    cudaFuncSetAttribute(qkv_f16,    cudaFuncAttributeMaxDynamicSharedMemorySize, SMEM_DYN);
    cudaFuncSetAttribute(scores_f16, cudaFuncAttributeMaxDynamicSharedMemorySize, SMEM_DYN);
    cudaFuncSetAttribute(pv_f16,     cudaFuncAttributeMaxDynamicSharedMemorySize, SMEM_DYN);

    cvt_x_kernel<<<(int)(((size_t)MM * DD / 4) / 256), 256>>>(x);
    transW_kernel<<<dim3(32, 32, 3), dim3(32, 8)>>>(Wq, Wk, Wv);
    qkv_f16<<<dim3(DD / CTA_N, MM / CTA_M, 3), TPB, SMEM_DYN>>>();
    transV_kernel<<<dim3(DD / 32, SS / 32, BB), dim3(32, 8)>>>();
    scores_f16<<<dim3(SS / CTA_N, SS / CTA_M, BB), TPB, SMEM_DYN>>>();
    softmax_kernel<<<dim3(SS, BB), 256>>>();
    pv_f16<<<dim3(DD / CTA_N, SS / CTA_M, BB), TPB, SMEM_DYN>>>(out);
}